// round 8
// baseline (speedup 1.0000x reference)
#include <cuda_runtime.h>
#include <math.h>

#define NUM_U 100000
#define NUM_I 50000
#define N_ER  1000000
#define N_ET  800000
#define N_EP  200000
#define EMB   64
#define CAT   192   // EMB * (1 + L), L = 2

// ---------------- scratch (device globals; no runtime allocation) ----------------
__device__ float    g_hu[NUM_U * EMB];
__device__ float    g_hi[NUM_I * EMB];
__device__ float    g_hi_new[NUM_I * EMB];
__device__ float    g_fs[NUM_U * EMB];      // transformed source feats (max NU rows)
__device__ float    g_fd[NUM_U * EMB];      // transformed dst feats
__device__ float    g_p[NUM_U * EMB];
__device__ float    g_q[NUM_U * EMB];
__device__ float    g_out[NUM_U * EMB];     // GAT aggregation buffer
__device__ float    g_e[N_ER];              // per-edge exp(logit)
__device__ float    g_den[NUM_U];           // segment sum of exp
__device__ float    g_hu_all[(size_t)NUM_U * CAT];
__device__ float    g_hi_all[(size_t)NUM_I * CAT];
__device__ float    g_z[2 * NUM_U];         // [0:NU)=z_inf, [NU:2NU)=z_int
__device__ double   g_bn[4];                // sum/sumsq for both gates
__device__ float    g_v[2 * 2 * EMB];       // folded attention vectors (2 gates x 128)
__device__ float    g_cc[2];                // folded attention consts

// ---------------- helpers ----------------
__device__ __forceinline__ float lrelu(float x, float s) { return x > 0.f ? x : s * x; }

__device__ __forceinline__ void red_add_v4(float* p, float4 v) {
    asm volatile("red.global.add.v4.f32 [%0], {%1, %2, %3, %4};"
                 :: "l"(p), "f"(v.x), "f"(v.y), "f"(v.z), "f"(v.w) : "memory");
}

__device__ __forceinline__ float4 ldg4(const float* p) {
    return __ldg((const float4*)p);
}

// ---------------- kernels ----------------

// y[n,64] = x[n,64] @ W[64,64] + b ; src_sel: 0=g_hu 1=g_hi ; dst_sel: 0=g_fs 1=g_fd
__global__ __launch_bounds__(256) void k_linear(int src_sel, int dst_sel,
                                                const float* __restrict__ W,
                                                const float* __restrict__ b, int n) {
    __shared__ float Ws[EMB * EMB];
    __shared__ float xs[32][EMB];
    __shared__ float bs[EMB];
    const float* x = src_sel == 0 ? g_hu : g_hi;
    float*       y = dst_sel == 0 ? g_fs : g_fd;
    int tid = threadIdx.x;
    for (int i = tid; i < EMB * EMB; i += 256) Ws[i] = W[i];
    if (tid < EMB) bs[tid] = b[tid];
    int row0 = blockIdx.x * 32;
    for (int i = tid; i < 32 * EMB; i += 256) {
        int r = i >> 6, c = i & 63;
        int row = row0 + r;
        xs[r][c] = (row < n) ? x[(size_t)row * EMB + c] : 0.f;
    }
    __syncthreads();
    int c = tid & 63;
    int rg = tid >> 6;  // 0..3, 8 rows each
    float acc[8];
#pragma unroll
    for (int j = 0; j < 8; j++) acc[j] = bs[c];
#pragma unroll
    for (int k = 0; k < EMB; k++) {
        float w = Ws[k * EMB + c];
#pragma unroll
        for (int j = 0; j < 8; j++) acc[j] += xs[rg * 8 + j][k] * w;
    }
#pragma unroll
    for (int j = 0; j < 8; j++) {
        int row = row0 + rg * 8 + j;
        if (row < n) y[(size_t)row * EMB + c] = acc[j];
    }
}

// zero den[n] and out[n*EMB] (vectorized)
__global__ __launch_bounds__(256) void k_gat_init(int n) {
    int i = blockIdx.x * blockDim.x + threadIdx.x;
    if (i < n) g_den[i] = 0.f;
    if (i < n * (EMB / 4)) ((float4*)g_out)[i] = make_float4(0.f, 0.f, 0.f, 0.f);
}

// half-warp (16 lanes) per edge, float4 loads:
// e = attn . leaky_relu(fs[src]+fd[dst], 0.2); ex = exp(e); den[dst] += ex
// (max-shift dropped: logits are O(0.1) for this init; clamp at 50 is a no-op in
//  that regime and merely prevents inf/NaN if the scale assumption ever breaks)
__global__ __launch_bounds__(256) void k_edge_pass1(const int* __restrict__ src,
                                                    const int* __restrict__ dst,
                                                    const float* __restrict__ attn, int nE) {
    int idx = blockIdx.x * blockDim.x + threadIdx.x;
    int e = idx >> 4;
    int lane = threadIdx.x & 15;
    if (e >= nE) return;
    int s = __ldg(src + e), d = __ldg(dst + e);
    float4 a = ldg4(g_fs + (size_t)s * EMB + lane * 4);
    float4 b = ldg4(g_fd + (size_t)d * EMB + lane * 4);
    float4 at = ldg4(attn + lane * 4);
    float v = lrelu(a.x + b.x, 0.2f) * at.x + lrelu(a.y + b.y, 0.2f) * at.y +
              lrelu(a.z + b.z, 0.2f) * at.z + lrelu(a.w + b.w, 0.2f) * at.w;
    unsigned m = 0xffffu << (threadIdx.x & 16);   // own half-warp only
#pragma unroll
    for (int o = 8; o; o >>= 1) v += __shfl_xor_sync(m, v, o);
    if (lane == 0) {
        float ex = expf(fminf(v, 50.f));
        g_e[e] = ex;
        atomicAdd(&g_den[d], ex);
    }
}

// half-warp per edge: out[dst] += (ex/den[dst]) * fs[src], vector reductions
__global__ __launch_bounds__(256) void k_edge_pass2(const int* __restrict__ src,
                                                    const int* __restrict__ dst, int nE) {
    int idx = blockIdx.x * blockDim.x + threadIdx.x;
    int e = idx >> 4;
    int lane = threadIdx.x & 15;
    if (e >= nE) return;
    int s = __ldg(src + e), d = __ldg(dst + e);
    float alpha = __ldg(g_e + e) / __ldg(g_den + d);
    float4 a = ldg4(g_fs + (size_t)s * EMB + lane * 4);
    a.x *= alpha; a.y *= alpha; a.z *= alpha; a.w *= alpha;
    red_add_v4(g_out + (size_t)d * EMB + lane * 4, a);
}

// dst_sel: 0 -> g_hi_new = out + bias + g_hi ; 1 -> g_q = out + bias ; 2 -> g_p = out + bias
// i indexes float4 over n*16
__global__ __launch_bounds__(256) void k_gat_final(int dst_sel, const float* __restrict__ bias,
                                                   int n) {
    int i = blockIdx.x * blockDim.x + threadIdx.x;
    if (i >= n * (EMB / 4)) return;
    float4 o = ((const float4*)g_out)[i];
    float4 bv = ldg4(bias + (i & 15) * 4);
    o.x += bv.x; o.y += bv.y; o.z += bv.z; o.w += bv.w;
    if (dst_sel == 0) {
        float4 h = ((const float4*)g_hi)[i];
        o.x += h.x; o.y += h.y; o.z += h.z; o.w += h.w;
        ((float4*)g_hi_new)[i] = o;
    } else if (dst_sel == 1) ((float4*)g_q)[i] = o;
    else                     ((float4*)g_p)[i] = o;
}

// fold (W1 @ W2) and (b1 . W2 + b2) for both gates; also reset BN accumulators
__global__ __launch_bounds__(256) void k_att_fold(const float* __restrict__ W1,
                                                  const float* __restrict__ b1,
                                                  const float* __restrict__ W2,
                                                  const float* __restrict__ b2) {
    int tid = threadIdx.x;       // 256 = 2 gates x 128 rows
    int g = tid >> 7, j = tid & 127;
    const float* w1 = W1 + (size_t)g * 2 * EMB * 2 * EMB + (size_t)j * 2 * EMB;
    const float* w2 = W2 + (size_t)g * 2 * EMB;
    float acc = 0.f;
#pragma unroll
    for (int k = 0; k < 2 * EMB; k++) acc += w1[k] * w2[k];
    g_v[g * 2 * EMB + j] = acc;
    if (j == 0) {
        float c = b2[g];
        const float* bb = b1 + (size_t)g * 2 * EMB;
        for (int k = 0; k < 2 * EMB; k++) c += bb[k] * w2[k];
        g_cc[g] = c;
    }
    if (tid < 4) g_bn[tid] = 0.0;
}

// warp per user: z_inf = [hu,p].v_inf + c_inf ; z_int = [hu,q].v_int + c_int ; BN stats
__global__ __launch_bounds__(256) void k_z() {
    int u = (blockIdx.x * blockDim.x + threadIdx.x) >> 5;
    int lane = threadIdx.x & 31;
    if (u >= NUM_U) return;
    const float* hr = g_hu + (size_t)u * EMB;
    const float* pr = g_p + (size_t)u * EMB;
    const float* qr = g_q + (size_t)u * EMB;
    float h0 = hr[lane], h1 = hr[lane + 32];
    float p0 = pr[lane], p1 = pr[lane + 32];
    float q0 = qr[lane], q1 = qr[lane + 32];
    float zi = h0 * g_v[lane] + h1 * g_v[lane + 32] + p0 * g_v[64 + lane] + p1 * g_v[96 + lane];
    float zt = h0 * g_v[128 + lane] + h1 * g_v[160 + lane] + q0 * g_v[192 + lane] + q1 * g_v[224 + lane];
#pragma unroll
    for (int o = 16; o; o >>= 1) {
        zi += __shfl_xor_sync(0xffffffffu, zi, o);
        zt += __shfl_xor_sync(0xffffffffu, zt, o);
    }
    if (lane == 0) {
        zi += g_cc[0];
        zt += g_cc[1];
        g_z[u] = zi;
        g_z[NUM_U + u] = zt;
        atomicAdd(&g_bn[0], (double)zi);
        atomicAdd(&g_bn[1], (double)zi * (double)zi);
        atomicAdd(&g_bn[2], (double)zt);
        atomicAdd(&g_bn[3], (double)zt * (double)zt);
    }
}

// per (u, k4): BN -> leaky(0.01) -> softmax gate -> hu update; also write concat buffer
__global__ __launch_bounds__(256) void k_gate(int col0) {
    int i = blockIdx.x * blockDim.x + threadIdx.x;
    if (i >= NUM_U * (EMB / 4)) return;
    int u = i >> 4, k4 = i & 15;
    const double inv = 1.0 / (double)NUM_U;
    double mu0 = g_bn[0] * inv, mu1 = g_bn[2] * inv;
    double var0 = g_bn[1] * inv - mu0 * mu0;
    double var1 = g_bn[3] * inv - mu1 * mu1;
    float r0 = rsqrtf((float)var0 + 1e-5f);
    float r1 = rsqrtf((float)var1 + 1e-5f);
    float a0 = lrelu((g_z[u] - (float)mu0) * r0, 0.01f);
    float a1 = lrelu((g_z[NUM_U + u] - (float)mu1) * r1, 0.01f);
    float mx = fmaxf(a0, a1);
    float e0 = expf(a0 - mx), e1 = expf(a1 - mx);
    float is = 1.f / (e0 + e1);
    float g0 = e0 * is, g1 = e1 * is;
    float4 pv = ((const float4*)g_p)[i];
    float4 qv = ((const float4*)g_q)[i];
    float4 hv = ((const float4*)g_hu)[i];
    float4 v;
    v.x = g0 * pv.x + g1 * qv.x + hv.x;
    v.y = g0 * pv.y + g1 * qv.y + hv.y;
    v.z = g0 * pv.z + g1 * qv.z + hv.z;
    v.w = g0 * pv.w + g1 * qv.w + hv.w;
    ((float4*)g_hu)[i] = v;
    ((float4*)(g_hu_all + (size_t)u * CAT + col0))[k4] = v;
}

// copy external src into (h, h_all) ; target 0=user 1=item (vectorized)
__global__ __launch_bounds__(256) void k_set_layer(const float* __restrict__ src, int target,
                                                   int col0, int n) {
    int i = blockIdx.x * blockDim.x + threadIdx.x;
    if (i >= n * (EMB / 4)) return;
    int u = i >> 4, k4 = i & 15;
    float4 v = ldg4(src + (size_t)i * 4);
    if (target == 0) {
        ((float4*)g_hu)[i] = v;
        ((float4*)(g_hu_all + (size_t)u * CAT + col0))[k4] = v;
    } else {
        ((float4*)g_hi)[i] = v;
        ((float4*)(g_hi_all + (size_t)u * CAT + col0))[k4] = v;
    }
}

__global__ __launch_bounds__(256) void k_commit_hi(int col0) {
    int i = blockIdx.x * blockDim.x + threadIdx.x;
    if (i >= NUM_I * (EMB / 4)) return;
    int u = i >> 4, k4 = i & 15;
    float4 v = ((const float4*)g_hi_new)[i];
    ((float4*)g_hi)[i] = v;
    ((float4*)(g_hi_all + (size_t)u * CAT + col0))[k4] = v;
}

// half-warp per pair: dot of 192-dim concat embeddings via 3x float4 per lane
__global__ __launch_bounds__(256) void k_dot(const int* __restrict__ pu, const int* __restrict__ pi,
                                             const int* __restrict__ nu, const int* __restrict__ ni,
                                             float* __restrict__ out) {
    int idx = blockIdx.x * blockDim.x + threadIdx.x;
    int j = idx >> 4;
    int lane = threadIdx.x & 15;
    if (j >= 2 * N_EP) return;
    int u, it;
    if (j < N_EP) { u = __ldg(pu + j); it = __ldg(pi + j); }
    else          { u = __ldg(nu + j - N_EP); it = __ldg(ni + j - N_EP); }
    const float* a = g_hu_all + (size_t)u * CAT;
    const float* b = g_hi_all + (size_t)it * CAT;
    float s = 0.f;
#pragma unroll
    for (int t = 0; t < 3; t++) {
        float4 av = ldg4(a + (lane + 16 * t) * 4);
        float4 bv = ldg4(b + (lane + 16 * t) * 4);
        s += av.x * bv.x + av.y * bv.y + av.z * bv.z + av.w * bv.w;
    }
    unsigned m = 0xffffu << (threadIdx.x & 16);   // own half-warp only
#pragma unroll
    for (int o = 8; o; o >>= 1) s += __shfl_xor_sync(m, s, o);
    if (lane == 0) out[j] = s;
}

// ---------------- host ----------------
static inline int nblk(long n) { return (int)((n + 255) / 256); }

extern "C" void kernel_launch(void* const* d_in, const int* in_sizes, int n_in,
                              void* d_out, int out_size) {
    const float *eu, *ei, *rate_W, *rate_b, *rate_attn, *rate_bias;
    const float *rb_W, *rb_b, *rb_attn, *rb_bias, *tr_W, *tr_b, *tr_attn, *tr_bias;
    const float *attW1, *attb1, *attW2, *attb2;
    const int *rate_src, *rate_dst, *trust_src, *trust_dst, *pos_u, *pos_i, *neg_u, *neg_i;

    if (in_sizes[0] == NUM_U * EMB) {
        // reference-signature order
        eu = (const float*)d_in[0];   ei = (const float*)d_in[1];
        rate_W = (const float*)d_in[2];  rate_b = (const float*)d_in[3];
        rate_attn = (const float*)d_in[4]; rate_bias = (const float*)d_in[5];
        rb_W = (const float*)d_in[6];  rb_b = (const float*)d_in[7];
        rb_attn = (const float*)d_in[8]; rb_bias = (const float*)d_in[9];
        tr_W = (const float*)d_in[10]; tr_b = (const float*)d_in[11];
        tr_attn = (const float*)d_in[12]; tr_bias = (const float*)d_in[13];
        attW1 = (const float*)d_in[14]; attb1 = (const float*)d_in[15];
        attW2 = (const float*)d_in[16]; attb2 = (const float*)d_in[17];
        rate_src = (const int*)d_in[18]; rate_dst = (const int*)d_in[19];
        trust_src = (const int*)d_in[20]; trust_dst = (const int*)d_in[21];
        pos_u = (const int*)d_in[22]; pos_i = (const int*)d_in[23];
        neg_u = (const int*)d_in[24]; neg_i = (const int*)d_in[25];
    } else {
        // setup_inputs dict order
        rate_src = (const int*)d_in[0]; rate_dst = (const int*)d_in[1];
        trust_src = (const int*)d_in[2]; trust_dst = (const int*)d_in[3];
        pos_u = (const int*)d_in[4]; pos_i = (const int*)d_in[5];
        neg_u = (const int*)d_in[6]; neg_i = (const int*)d_in[7];
        eu = (const float*)d_in[8];  ei = (const float*)d_in[9];
        rate_W = (const float*)d_in[10]; rate_b = (const float*)d_in[11];
        rate_attn = (const float*)d_in[12]; rate_bias = (const float*)d_in[13];
        rb_W = (const float*)d_in[14]; rb_b = (const float*)d_in[15];
        rb_attn = (const float*)d_in[16]; rb_bias = (const float*)d_in[17];
        tr_W = (const float*)d_in[18]; tr_b = (const float*)d_in[19];
        tr_attn = (const float*)d_in[20]; tr_bias = (const float*)d_in[21];
        attW1 = (const float*)d_in[22]; attb1 = (const float*)d_in[23];
        attW2 = (const float*)d_in[24]; attb2 = (const float*)d_in[25];
    }

    // init: layer-0 columns of concat buffers + working embeddings
    k_set_layer<<<nblk((long)NUM_U * 16), 256>>>(eu, 0, 0, NUM_U);
    k_set_layer<<<nblk((long)NUM_I * 16), 256>>>(ei, 1, 0, NUM_I);

    for (int l = 0; l < 2; l++) {
        const size_t wo = (size_t)l * 2 * EMB * EMB;   // per-layer W offset
        const size_t bo = (size_t)l * 2 * EMB;         // per-layer b offset
        const size_t ao = (size_t)l * EMB;             // per-layer attn/bias offset

        // ---- rate GAT (user -> item), dst = items ----
        k_linear<<<(NUM_U + 31) / 32, 256>>>(0, 0, rate_W + wo, rate_b + bo, NUM_U);
        k_linear<<<(NUM_I + 31) / 32, 256>>>(1, 1, rate_W + wo + EMB * EMB, rate_b + bo + EMB, NUM_I);
        k_gat_init<<<nblk((long)NUM_I * 16), 256>>>(NUM_I);
        k_edge_pass1<<<nblk((long)N_ER * 16), 256>>>(rate_src, rate_dst, rate_attn + ao, N_ER);
        k_edge_pass2<<<nblk((long)N_ER * 16), 256>>>(rate_src, rate_dst, N_ER);
        k_gat_final<<<nblk((long)NUM_I * 16), 256>>>(0, rate_bias + ao, NUM_I);

        // ---- rated-by GAT (item -> user), dst = users (reverse edges) ----
        k_linear<<<(NUM_I + 31) / 32, 256>>>(1, 0, rb_W + wo, rb_b + bo, NUM_I);
        k_linear<<<(NUM_U + 31) / 32, 256>>>(0, 1, rb_W + wo + EMB * EMB, rb_b + bo + EMB, NUM_U);
        k_gat_init<<<nblk((long)NUM_U * 16), 256>>>(NUM_U);
        k_edge_pass1<<<nblk((long)N_ER * 16), 256>>>(rate_dst, rate_src, rb_attn + ao, N_ER);
        k_edge_pass2<<<nblk((long)N_ER * 16), 256>>>(rate_dst, rate_src, N_ER);
        k_gat_final<<<nblk((long)NUM_U * 16), 256>>>(1, rb_bias + ao, NUM_U);

        // ---- trust GAT (user -> user) ----
        k_linear<<<(NUM_U + 31) / 32, 256>>>(0, 0, tr_W + wo, tr_b + bo, NUM_U);
        k_linear<<<(NUM_U + 31) / 32, 256>>>(0, 1, tr_W + wo + EMB * EMB, tr_b + bo + EMB, NUM_U);
        k_gat_init<<<nblk((long)NUM_U * 16), 256>>>(NUM_U);
        k_edge_pass1<<<nblk((long)N_ET * 16), 256>>>(trust_src, trust_dst, tr_attn + ao, N_ET);
        k_edge_pass2<<<nblk((long)N_ET * 16), 256>>>(trust_src, trust_dst, N_ET);
        k_gat_final<<<nblk((long)NUM_U * 16), 256>>>(2, tr_bias + ao, NUM_U);

        // ---- attention gating ----
        k_att_fold<<<1, 256>>>(attW1 + (size_t)l * 2 * 2 * EMB * 2 * EMB,
                               attb1 + (size_t)l * 2 * 2 * EMB,
                               attW2 + (size_t)l * 2 * 2 * EMB,
                               attb2 + (size_t)l * 2);
        k_z<<<nblk((long)NUM_U * 32), 256>>>();
        k_gate<<<nblk((long)NUM_U * 16), 256>>>(EMB * (l + 1));
        k_commit_hi<<<nblk((long)NUM_I * 16), 256>>>(EMB * (l + 1));
    }

    // ---- final pos/neg dots ----
    k_dot<<<nblk((long)2 * N_EP * 16), 256>>>(pos_u, pos_i, neg_u, neg_i, (float*)d_out);
}

// round 12
// speedup vs baseline: 1.2041x; 1.2041x over previous
#include <cuda_runtime.h>
#include <math.h>

#define NUM_U 100000
#define NUM_I 50000
#define N_ER  1000000
#define N_ET  800000
#define N_EP  200000
#define EMB   64
#define CAT   192   // EMB * (1 + L), L = 2

// ---------------- scratch (device globals; no runtime allocation) ----------------
__device__ float    g_hu[NUM_U * EMB];
__device__ float    g_hi[NUM_I * EMB];
__device__ float    g_hi_new[NUM_I * EMB];
__device__ float    g_fs[NUM_U * EMB];      // transformed source feats (max NU rows)
__device__ float    g_fd[NUM_U * EMB];      // transformed dst feats
__device__ float    g_p[NUM_U * EMB];
__device__ float    g_q[NUM_U * EMB];
__device__ float    g_out[NUM_U * EMB];     // GAT aggregation buffer (unnormalized)
__device__ float    g_den[NUM_U];           // segment sum of exp
__device__ float    g_hu_all[(size_t)NUM_U * CAT];
__device__ float    g_hi_all[(size_t)NUM_I * CAT];
__device__ float    g_z[2 * NUM_U];         // [0:NU)=z_inf, [NU:2NU)=z_int
__device__ double   g_bn[4];                // sum/sumsq for both gates
__device__ float    g_v[2 * 2 * EMB];       // folded attention vectors (2 gates x 128)
__device__ float    g_cc[2];                // folded attention consts

// ---------------- helpers ----------------
__device__ __forceinline__ float lrelu(float x, float s) { return x > 0.f ? x : s * x; }

__device__ __forceinline__ void red_add_v4(float* p, float4 v) {
    asm volatile("red.global.add.v4.f32 [%0], {%1, %2, %3, %4};"
                 :: "l"(p), "f"(v.x), "f"(v.y), "f"(v.z), "f"(v.w) : "memory");
}

__device__ __forceinline__ float4 ldg4(const float* p) {
    return __ldg((const float4*)p);
}

// ---------------- kernels ----------------

// y[n,64] = x[n,64] @ W[64,64] + b ; src_sel: 0=g_hu 1=g_hi ; dst_sel: 0=g_fs 1=g_fd
__global__ __launch_bounds__(256) void k_linear(int src_sel, int dst_sel,
                                                const float* __restrict__ W,
                                                const float* __restrict__ b, int n) {
    __shared__ float Ws[EMB * EMB];
    __shared__ float xs[32][EMB];
    __shared__ float bs[EMB];
    const float* x = src_sel == 0 ? g_hu : g_hi;
    float*       y = dst_sel == 0 ? g_fs : g_fd;
    int tid = threadIdx.x;
    // vectorized smem fills (W, b, x are all 16B-aligned: offsets are multiples of 64 floats)
    for (int i = tid; i < EMB * EMB / 4; i += 256) ((float4*)Ws)[i] = ldg4(W + i * 4);
    if (tid < EMB / 4) ((float4*)bs)[tid] = ldg4(b + tid * 4);
    int row0 = blockIdx.x * 32;
    for (int i = tid; i < 32 * (EMB / 4); i += 256) {
        int r = i >> 4, c4 = i & 15;
        int row = row0 + r;
        float4 v = (row < n) ? ldg4(x + (size_t)row * EMB + c4 * 4)
                             : make_float4(0.f, 0.f, 0.f, 0.f);
        ((float4*)&xs[r][0])[c4] = v;
    }
    __syncthreads();
    int c = tid & 63;
    int rg = tid >> 6;  // 0..3, 8 rows each
    float acc[8];
#pragma unroll
    for (int j = 0; j < 8; j++) acc[j] = bs[c];
#pragma unroll
    for (int k = 0; k < EMB; k++) {
        float w = Ws[k * EMB + c];
#pragma unroll
        for (int j = 0; j < 8; j++) acc[j] += xs[rg * 8 + j][k] * w;
    }
#pragma unroll
    for (int j = 0; j < 8; j++) {
        int row = row0 + rg * 8 + j;
        if (row < n) y[(size_t)row * EMB + c] = acc[j];
    }
}

// zero den[n] and out[n*EMB] (vectorized)
__global__ __launch_bounds__(256) void k_gat_init(int n) {
    int i = blockIdx.x * blockDim.x + threadIdx.x;
    if (i < n) g_den[i] = 0.f;
    if (i < n * (EMB / 4)) ((float4*)g_out)[i] = make_float4(0.f, 0.f, 0.f, 0.f);
}

// SINGLE fused edge pass, half-warp (16 lanes) per edge, float4 loads:
//   e  = attn . leaky_relu(fs[src]+fd[dst], 0.2)
//   ex = exp(e)                       (max-shift deferred-normalization form:
//   den[dst] += ex                     out_raw[dst] += ex*fs; divide by den at
//   out_raw[dst] += ex * fs[src]       node level — exactly softmax-weighted sum)
__global__ __launch_bounds__(256) void k_edge(const int* __restrict__ src,
                                              const int* __restrict__ dst,
                                              const float* __restrict__ attn, int nE) {
    int idx = blockIdx.x * blockDim.x + threadIdx.x;
    int e = idx >> 4;
    int lane = threadIdx.x & 15;
    if (e >= nE) return;
    int s = __ldg(src + e), d = __ldg(dst + e);
    float4 a = ldg4(g_fs + (size_t)s * EMB + lane * 4);
    float4 b = ldg4(g_fd + (size_t)d * EMB + lane * 4);
    float4 at = ldg4(attn + lane * 4);
    float v = lrelu(a.x + b.x, 0.2f) * at.x + lrelu(a.y + b.y, 0.2f) * at.y +
              lrelu(a.z + b.z, 0.2f) * at.z + lrelu(a.w + b.w, 0.2f) * at.w;
    unsigned m = 0xffffu << (threadIdx.x & 16);   // own half-warp only
#pragma unroll
    for (int o = 8; o; o >>= 1) v += __shfl_xor_sync(m, v, o);
    // butterfly leaves the full 64-dim dot in every lane
    float ex = expf(fminf(v, 50.f));   // logits are O(0.1) at this init; clamp = NaN guard only
    if (lane == 0) atomicAdd(&g_den[d], ex);
    a.x *= ex; a.y *= ex; a.z *= ex; a.w *= ex;
    red_add_v4(g_out + (size_t)d * EMB + lane * 4, a);
}

// normalize by den (guarded: empty segments -> 0, matching reference's empty segsum),
// add bias; dst_sel: 0 -> g_hi_new = . + g_hi ; 1 -> g_q ; 2 -> g_p
__global__ __launch_bounds__(256) void k_gat_final(int dst_sel, const float* __restrict__ bias,
                                                   int n) {
    int i = blockIdx.x * blockDim.x + threadIdx.x;
    if (i >= n * (EMB / 4)) return;
    int u = i >> 4;
    float den = g_den[u];
    float dinv = den > 0.f ? 1.f / den : 0.f;
    float4 o = ((const float4*)g_out)[i];
    float4 bv = ldg4(bias + (i & 15) * 4);
    o.x = o.x * dinv + bv.x; o.y = o.y * dinv + bv.y;
    o.z = o.z * dinv + bv.z; o.w = o.w * dinv + bv.w;
    if (dst_sel == 0) {
        float4 h = ((const float4*)g_hi)[i];
        o.x += h.x; o.y += h.y; o.z += h.z; o.w += h.w;
        ((float4*)g_hi_new)[i] = o;
    } else if (dst_sel == 1) ((float4*)g_q)[i] = o;
    else                     ((float4*)g_p)[i] = o;
}

// fold (W1 @ W2) and (b1 . W2 + b2) for both gates; also reset BN accumulators
__global__ __launch_bounds__(256) void k_att_fold(const float* __restrict__ W1,
                                                  const float* __restrict__ b1,
                                                  const float* __restrict__ W2,
                                                  const float* __restrict__ b2) {
    int tid = threadIdx.x;       // 256 = 2 gates x 128 rows
    int g = tid >> 7, j = tid & 127;
    const float* w1 = W1 + (size_t)g * 2 * EMB * 2 * EMB + (size_t)j * 2 * EMB;
    const float* w2 = W2 + (size_t)g * 2 * EMB;
    float acc = 0.f;
#pragma unroll
    for (int k = 0; k < 2 * EMB; k++) acc += w1[k] * w2[k];
    g_v[g * 2 * EMB + j] = acc;
    if (j == 0) {
        float c = b2[g];
        const float* bb = b1 + (size_t)g * 2 * EMB;
        for (int k = 0; k < 2 * EMB; k++) c += bb[k] * w2[k];
        g_cc[g] = c;
    }
    if (tid < 4) g_bn[tid] = 0.0;
}

// warp per user: z_inf = [hu,p].v_inf + c_inf ; z_int = [hu,q].v_int + c_int ; BN stats
__global__ __launch_bounds__(256) void k_z() {
    int u = (blockIdx.x * blockDim.x + threadIdx.x) >> 5;
    int lane = threadIdx.x & 31;
    if (u >= NUM_U) return;
    const float* hr = g_hu + (size_t)u * EMB;
    const float* pr = g_p + (size_t)u * EMB;
    const float* qr = g_q + (size_t)u * EMB;
    float h0 = hr[lane], h1 = hr[lane + 32];
    float p0 = pr[lane], p1 = pr[lane + 32];
    float q0 = qr[lane], q1 = qr[lane + 32];
    float zi = h0 * g_v[lane] + h1 * g_v[lane + 32] + p0 * g_v[64 + lane] + p1 * g_v[96 + lane];
    float zt = h0 * g_v[128 + lane] + h1 * g_v[160 + lane] + q0 * g_v[192 + lane] + q1 * g_v[224 + lane];
#pragma unroll
    for (int o = 16; o; o >>= 1) {
        zi += __shfl_xor_sync(0xffffffffu, zi, o);
        zt += __shfl_xor_sync(0xffffffffu, zt, o);
    }
    if (lane == 0) {
        zi += g_cc[0];
        zt += g_cc[1];
        g_z[u] = zi;
        g_z[NUM_U + u] = zt;
        atomicAdd(&g_bn[0], (double)zi);
        atomicAdd(&g_bn[1], (double)zi * (double)zi);
        atomicAdd(&g_bn[2], (double)zt);
        atomicAdd(&g_bn[3], (double)zt * (double)zt);
    }
}

// per (u, k4): BN -> leaky(0.01) -> softmax gate -> hu update; also write concat buffer
__global__ __launch_bounds__(256) void k_gate(int col0) {
    int i = blockIdx.x * blockDim.x + threadIdx.x;
    if (i >= NUM_U * (EMB / 4)) return;
    int u = i >> 4, k4 = i & 15;
    const double inv = 1.0 / (double)NUM_U;
    double mu0 = g_bn[0] * inv, mu1 = g_bn[2] * inv;
    double var0 = g_bn[1] * inv - mu0 * mu0;
    double var1 = g_bn[3] * inv - mu1 * mu1;
    float r0 = rsqrtf((float)var0 + 1e-5f);
    float r1 = rsqrtf((float)var1 + 1e-5f);
    float a0 = lrelu((g_z[u] - (float)mu0) * r0, 0.01f);
    float a1 = lrelu((g_z[NUM_U + u] - (float)mu1) * r1, 0.01f);
    float mx = fmaxf(a0, a1);
    float e0 = expf(a0 - mx), e1 = expf(a1 - mx);
    float is = 1.f / (e0 + e1);
    float g0 = e0 * is, g1 = e1 * is;
    float4 pv = ((const float4*)g_p)[i];
    float4 qv = ((const float4*)g_q)[i];
    float4 hv = ((const float4*)g_hu)[i];
    float4 v;
    v.x = g0 * pv.x + g1 * qv.x + hv.x;
    v.y = g0 * pv.y + g1 * qv.y + hv.y;
    v.z = g0 * pv.z + g1 * qv.z + hv.z;
    v.w = g0 * pv.w + g1 * qv.w + hv.w;
    ((float4*)g_hu)[i] = v;
    ((float4*)(g_hu_all + (size_t)u * CAT + col0))[k4] = v;
}

// copy external src into (h, h_all) ; target 0=user 1=item (vectorized)
__global__ __launch_bounds__(256) void k_set_layer(const float* __restrict__ src, int target,
                                                   int col0, int n) {
    int i = blockIdx.x * blockDim.x + threadIdx.x;
    if (i >= n * (EMB / 4)) return;
    int u = i >> 4, k4 = i & 15;
    float4 v = ldg4(src + (size_t)i * 4);
    if (target == 0) {
        ((float4*)g_hu)[i] = v;
        ((float4*)(g_hu_all + (size_t)u * CAT + col0))[k4] = v;
    } else {
        ((float4*)g_hi)[i] = v;
        ((float4*)(g_hi_all + (size_t)u * CAT + col0))[k4] = v;
    }
}

__global__ __launch_bounds__(256) void k_commit_hi(int col0) {
    int i = blockIdx.x * blockDim.x + threadIdx.x;
    if (i >= NUM_I * (EMB / 4)) return;
    int u = i >> 4, k4 = i & 15;
    float4 v = ((const float4*)g_hi_new)[i];
    ((float4*)g_hi)[i] = v;
    ((float4*)(g_hi_all + (size_t)u * CAT + col0))[k4] = v;
}

// half-warp per pair: dot of 192-dim concat embeddings via 3x float4 per lane
__global__ __launch_bounds__(256) void k_dot(const int* __restrict__ pu, const int* __restrict__ pi,
                                             const int* __restrict__ nu, const int* __restrict__ ni,
                                             float* __restrict__ out) {
    int idx = blockIdx.x * blockDim.x + threadIdx.x;
    int j = idx >> 4;
    int lane = threadIdx.x & 15;
    if (j >= 2 * N_EP) return;
    int u, it;
    if (j < N_EP) { u = __ldg(pu + j); it = __ldg(pi + j); }
    else          { u = __ldg(nu + j - N_EP); it = __ldg(ni + j - N_EP); }
    const float* a = g_hu_all + (size_t)u * CAT;
    const float* b = g_hi_all + (size_t)it * CAT;
    float s = 0.f;
#pragma unroll
    for (int t = 0; t < 3; t++) {
        float4 av = ldg4(a + (lane + 16 * t) * 4);
        float4 bv = ldg4(b + (lane + 16 * t) * 4);
        s += av.x * bv.x + av.y * bv.y + av.z * bv.z + av.w * bv.w;
    }
    unsigned m = 0xffffu << (threadIdx.x & 16);   // own half-warp only
#pragma unroll
    for (int o = 8; o; o >>= 1) s += __shfl_xor_sync(m, s, o);
    if (lane == 0) out[j] = s;
}

// ---------------- host ----------------
static inline int nblk(long n) { return (int)((n + 255) / 256); }

extern "C" void kernel_launch(void* const* d_in, const int* in_sizes, int n_in,
                              void* d_out, int out_size) {
    const float *eu, *ei, *rate_W, *rate_b, *rate_attn, *rate_bias;
    const float *rb_W, *rb_b, *rb_attn, *rb_bias, *tr_W, *tr_b, *tr_attn, *tr_bias;
    const float *attW1, *attb1, *attW2, *attb2;
    const int *rate_src, *rate_dst, *trust_src, *trust_dst, *pos_u, *pos_i, *neg_u, *neg_i;

    if (in_sizes[0] == NUM_U * EMB) {
        // reference-signature order
        eu = (const float*)d_in[0];   ei = (const float*)d_in[1];
        rate_W = (const float*)d_in[2];  rate_b = (const float*)d_in[3];
        rate_attn = (const float*)d_in[4]; rate_bias = (const float*)d_in[5];
        rb_W = (const float*)d_in[6];  rb_b = (const float*)d_in[7];
        rb_attn = (const float*)d_in[8]; rb_bias = (const float*)d_in[9];
        tr_W = (const float*)d_in[10]; tr_b = (const float*)d_in[11];
        tr_attn = (const float*)d_in[12]; tr_bias = (const float*)d_in[13];
        attW1 = (const float*)d_in[14]; attb1 = (const float*)d_in[15];
        attW2 = (const float*)d_in[16]; attb2 = (const float*)d_in[17];
        rate_src = (const int*)d_in[18]; rate_dst = (const int*)d_in[19];
        trust_src = (const int*)d_in[20]; trust_dst = (const int*)d_in[21];
        pos_u = (const int*)d_in[22]; pos_i = (const int*)d_in[23];
        neg_u = (const int*)d_in[24]; neg_i = (const int*)d_in[25];
    } else {
        // setup_inputs dict order
        rate_src = (const int*)d_in[0]; rate_dst = (const int*)d_in[1];
        trust_src = (const int*)d_in[2]; trust_dst = (const int*)d_in[3];
        pos_u = (const int*)d_in[4]; pos_i = (const int*)d_in[5];
        neg_u = (const int*)d_in[6]; neg_i = (const int*)d_in[7];
        eu = (const float*)d_in[8];  ei = (const float*)d_in[9];
        rate_W = (const float*)d_in[10]; rate_b = (const float*)d_in[11];
        rate_attn = (const float*)d_in[12]; rate_bias = (const float*)d_in[13];
        rb_W = (const float*)d_in[14]; rb_b = (const float*)d_in[15];
        rb_attn = (const float*)d_in[16]; rb_bias = (const float*)d_in[17];
        tr_W = (const float*)d_in[18]; tr_b = (const float*)d_in[19];
        tr_attn = (const float*)d_in[20]; tr_bias = (const float*)d_in[21];
        attW1 = (const float*)d_in[22]; attb1 = (const float*)d_in[23];
        attW2 = (const float*)d_in[24]; attb2 = (const float*)d_in[25];
    }

    // init: layer-0 columns of concat buffers + working embeddings
    k_set_layer<<<nblk((long)NUM_U * 16), 256>>>(eu, 0, 0, NUM_U);
    k_set_layer<<<nblk((long)NUM_I * 16), 256>>>(ei, 1, 0, NUM_I);

    for (int l = 0; l < 2; l++) {
        const size_t wo = (size_t)l * 2 * EMB * EMB;   // per-layer W offset
        const size_t bo = (size_t)l * 2 * EMB;         // per-layer b offset
        const size_t ao = (size_t)l * EMB;             // per-layer attn/bias offset

        // ---- rate GAT (user -> item), dst = items ----
        k_linear<<<(NUM_U + 31) / 32, 256>>>(0, 0, rate_W + wo, rate_b + bo, NUM_U);
        k_linear<<<(NUM_I + 31) / 32, 256>>>(1, 1, rate_W + wo + EMB * EMB, rate_b + bo + EMB, NUM_I);
        k_gat_init<<<nblk((long)NUM_I * 16), 256>>>(NUM_I);
        k_edge<<<nblk((long)N_ER * 16), 256>>>(rate_src, rate_dst, rate_attn + ao, N_ER);
        k_gat_final<<<nblk((long)NUM_I * 16), 256>>>(0, rate_bias + ao, NUM_I);

        // ---- rated-by GAT (item -> user), dst = users (reverse edges) ----
        k_linear<<<(NUM_I + 31) / 32, 256>>>(1, 0, rb_W + wo, rb_b + bo, NUM_I);
        k_linear<<<(NUM_U + 31) / 32, 256>>>(0, 1, rb_W + wo + EMB * EMB, rb_b + bo + EMB, NUM_U);
        k_gat_init<<<nblk((long)NUM_U * 16), 256>>>(NUM_U);
        k_edge<<<nblk((long)N_ER * 16), 256>>>(rate_dst, rate_src, rb_attn + ao, N_ER);
        k_gat_final<<<nblk((long)NUM_U * 16), 256>>>(1, rb_bias + ao, NUM_U);

        // ---- trust GAT (user -> user) ----
        k_linear<<<(NUM_U + 31) / 32, 256>>>(0, 0, tr_W + wo, tr_b + bo, NUM_U);
        k_linear<<<(NUM_U + 31) / 32, 256>>>(0, 1, tr_W + wo + EMB * EMB, tr_b + bo + EMB, NUM_U);
        k_gat_init<<<nblk((long)NUM_U * 16), 256>>>(NUM_U);
        k_edge<<<nblk((long)N_ET * 16), 256>>>(trust_src, trust_dst, tr_attn + ao, N_ET);
        k_gat_final<<<nblk((long)NUM_U * 16), 256>>>(2, tr_bias + ao, NUM_U);

        // ---- attention gating ----
        k_att_fold<<<1, 256>>>(attW1 + (size_t)l * 2 * 2 * EMB * 2 * EMB,
                               attb1 + (size_t)l * 2 * 2 * EMB,
                               attW2 + (size_t)l * 2 * 2 * EMB,
                               attb2 + (size_t)l * 2);
        k_z<<<nblk((long)NUM_U * 32), 256>>>();
        k_gate<<<nblk((long)NUM_U * 16), 256>>>(EMB * (l + 1));
        k_commit_hi<<<nblk((long)NUM_I * 16), 256>>>(EMB * (l + 1));
    }

    // ---- final pos/neg dots ----
    k_dot<<<nblk((long)2 * N_EP * 16), 256>>>(pos_u, pos_i, neg_u, neg_i, (float*)d_out);
}